// round 17
// baseline (speedup 1.0000x reference)
#include <cuda_runtime.h>
#include <cstdint>

// GraphProjection, monolithic — converged configuration.
// Session: R4 coalesced scalar 90.1 -> R9 Cauchy zero shortcut 71.3 ->
// R10 aligned zero-fill 69.7 -> R12 warp-uniform clip-collapse 67.6 ->
// R14 parity pairs (tie) -> R15 streaming stores __stcs 63.9 ->
// R16 512-thr tie (worse profile; reverted to 256).
// Floor: 386MB output stream @ ~6.0TB/s ~= DRAM/LTS ceiling. R17: route the
// aligned full-sector zero-fill (59% of output bytes) through __stwt (L2
// bypass) to free LTS bandwidth for the gather path; data stores stay __stcs.

static constexpr int OUT_COLS = 963;

struct PrepOut {
    const float* A;
    const float* B;
    const float* Cc;
    const float* D;
    float wa, wb, wc, wd;
    bool xc, yc;
};

template <int C, int S>
__device__ __forceinline__ PrepOut prep(const float* __restrict__ feat,
                                        float x, float y) {
    float x1f = floorf(x), x2f = ceilf(x);
    float y1f = floorf(y), y2f = ceilf(y);
    int xi1 = (int)x1f, xi2 = (int)x2f, yi1 = (int)y1f, yi2 = (int)y2f;
    // JAX gather clamps; lower clamp also guards NaN->int conversion.
    if (xi1 < 0) xi1 = 0;
    if (yi1 < 0) yi1 = 0;
    if (xi2 < 0) xi2 = 0;
    if (yi2 < 0) yi2 = 0;
    if (xi1 > S - 1) xi1 = S - 1;
    if (yi1 > S - 1) yi1 = S - 1;
    if (xi2 > S - 1) xi2 = S - 1;
    if (yi2 > S - 1) yi2 = S - 1;
    PrepOut r;
    r.wa = (x2f - x) * (y2f - y);
    r.wb = (x - x1f) * (y2f - y);
    r.wc = (x2f - x) * (y - y1f);
    r.wd = (x - x1f) * (y - y1f);
    r.A = feat + (xi1 * S + yi1) * C;
    r.B = feat + (xi2 * S + yi1) * C;
    r.Cc = feat + (xi1 * S + yi2) * C;
    r.D = feat + (xi2 * S + yi2) * C;
    r.xc = (xi1 == xi2);
    r.yc = (yi1 == yi2);
    return r;
}

// Scalar path (even p): coalesced LDG.32 + streaming STG.32.
template <int C, int S>
__device__ __forceinline__ void bilerp_scalar(const float* __restrict__ feat,
                                              float x, float y,
                                              float* __restrict__ o, int lane) {
    PrepOut t = prep<C, S>(feat, x, y);
    if (t.xc && t.yc) {
        float wf = (t.wa + t.wb) + (t.wc + t.wd);
#pragma unroll
        for (int i = 0; i < C / 32; ++i) {
            int c = lane + 32 * i;
            __stcs(o + c, wf * __ldg(t.A + c));
        }
    } else if (t.xc) {
        float w0 = t.wa + t.wb, w1 = t.wc + t.wd;
#pragma unroll
        for (int i = 0; i < C / 32; ++i) {
            int c = lane + 32 * i;
            float a = __ldg(t.A + c);
            float cv = __ldg(t.Cc + c);
            __stcs(o + c, w0 * a + w1 * cv);
        }
    } else if (t.yc) {
        float w0 = t.wa + t.wc, w1 = t.wb + t.wd;
#pragma unroll
        for (int i = 0; i < C / 32; ++i) {
            int c = lane + 32 * i;
            float a = __ldg(t.A + c);
            float b = __ldg(t.B + c);
            __stcs(o + c, w0 * a + w1 * b);
        }
    } else {
#pragma unroll
        for (int i = 0; i < C / 32; ++i) {
            int c = lane + 32 * i;
            float a = __ldg(t.A + c);
            float b = __ldg(t.B + c);
            float cv = __ldg(t.Cc + c);
            float d = __ldg(t.D + c);
            __stcs(o + c, t.wa * a + t.wb * b + t.wc * cv + t.wd * d);
        }
    }
}

// Pair path (odd p): LDG.64 + aligned streaming STG.64.
template <int C, int S>
__device__ __forceinline__ void bilerp_pair(const float* __restrict__ feat,
                                            float x, float y,
                                            float* __restrict__ o, int lane) {
    PrepOut t = prep<C, S>(feat, x, y);
    const float2* A2 = (const float2*)t.A;
    const float2* B2 = (const float2*)t.B;
    const float2* C2 = (const float2*)t.Cc;
    const float2* D2 = (const float2*)t.D;
    if (t.xc && t.yc) {
        float wf = (t.wa + t.wb) + (t.wc + t.wd);
#pragma unroll
        for (int i = 0; i < C / 64; ++i) {
            int c2 = lane + 32 * i;
            float2 a = __ldg(A2 + c2);
            __stcs((float2*)(o + 2 * c2), make_float2(wf * a.x, wf * a.y));
        }
    } else if (t.xc) {
        float w0 = t.wa + t.wb, w1 = t.wc + t.wd;
#pragma unroll
        for (int i = 0; i < C / 64; ++i) {
            int c2 = lane + 32 * i;
            float2 a = __ldg(A2 + c2);
            float2 cv = __ldg(C2 + c2);
            __stcs((float2*)(o + 2 * c2),
                   make_float2(w0 * a.x + w1 * cv.x, w0 * a.y + w1 * cv.y));
        }
    } else if (t.yc) {
        float w0 = t.wa + t.wc, w1 = t.wb + t.wd;
#pragma unroll
        for (int i = 0; i < C / 64; ++i) {
            int c2 = lane + 32 * i;
            float2 a = __ldg(A2 + c2);
            float2 b = __ldg(B2 + c2);
            __stcs((float2*)(o + 2 * c2),
                   make_float2(w0 * a.x + w1 * b.x, w0 * a.y + w1 * b.y));
        }
    } else {
#pragma unroll
        for (int i = 0; i < C / 64; ++i) {
            int c2 = lane + 32 * i;
            float2 a = __ldg(A2 + c2);
            float2 b = __ldg(B2 + c2);
            float2 cv = __ldg(C2 + c2);
            float2 d = __ldg(D2 + c2);
            __stcs((float2*)(o + 2 * c2),
                   make_float2(
                       t.wa * a.x + t.wb * b.x + t.wc * cv.x + t.wd * d.x,
                       t.wa * a.y + t.wb * b.y + t.wc * cv.y + t.wd * d.y));
        }
    }
}

__global__ void __launch_bounds__(256)
graph_projection_kernel(const float* __restrict__ coord,
                        const float* __restrict__ f1,
                        const float* __restrict__ f2,
                        const float* __restrict__ f3,
                        const float* __restrict__ f4,
                        float* __restrict__ out, int N) {
    int p = (blockIdx.x * blockDim.x + threadIdx.x) >> 5;  // warp = point
    int lane = threadIdx.x & 31;
    if (p >= N) return;

    float X = __ldg(coord + 3 * p + 0);
    float Y = __ldg(coord + 3 * p + 1);
    float Z = __ldg(coord + 3 * p + 2);

    float h = 250.0f * (-Y) / (-Z) + 112.0f;
    float w = 250.0f * X / (-Z) + 112.0f;
    // clip to [0,223]; comparison form preserves jnp.clip NaN propagation
    h = (h < 0.0f) ? 0.0f : ((h > 223.0f) ? 223.0f : h);
    w = (w < 0.0f) ? 0.0f : ((w > 223.0f) ? 223.0f : w);

    float* __restrict__ orow = out + (size_t)p * OUT_COLS;
    if (lane == 0) __stcs(orow + 0, X);
    if (lane == 1) __stcs(orow + 1, Y);
    if (lane == 2) __stcs(orow + 2, Z);

    // Fast path: h==0 or w==0 => all bilinear weights exactly 0.
    // Aligned full-sector zero body goes write-through (L2 bypass).
    if (h == 0.0f || w == 0.0f) {
        float* z = orow + 3;
        int head = (int)(((16u - ((uint32_t)(uintptr_t)z & 15u)) & 15u) >> 2);
        if (lane < head) __stcs(z + lane, 0.0f);
        int nvec = (960 - head) >> 2;
        float4* v = (float4*)(z + head);
        float4 z4 = make_float4(0.f, 0.f, 0.f, 0.f);
#pragma unroll
        for (int i = 0; i < 8; ++i) {
            int idx = lane + 32 * i;
            if (idx < nvec) __stwt(v + idx, z4);
        }
        int done = head + 4 * nvec;
        if (lane < 960 - done) __stcs(z + done + lane, 0.0f);
        return;
    }

    // scales: 224/56=4, 224/28=8, 224/14=16, 224/7=32 (exact pow2 -> mul ok)
    if (p & 1) {
        // odd p: 963p+base even for all bases (3,67,195,451) -> 8B aligned
        bilerp_pair<64, 56>(f1, h * 0.25f,    w * 0.25f,    orow + 3,   lane);
        bilerp_pair<128, 28>(f2, h * 0.125f,  w * 0.125f,   orow + 67,  lane);
        bilerp_pair<256, 14>(f3, h * 0.0625f, w * 0.0625f,  orow + 195, lane);
        bilerp_pair<512, 7>(f4, h * 0.03125f, w * 0.03125f, orow + 451, lane);
    } else {
        bilerp_scalar<64, 56>(f1, h * 0.25f,    w * 0.25f,    orow + 3,   lane);
        bilerp_scalar<128, 28>(f2, h * 0.125f,  w * 0.125f,   orow + 67,  lane);
        bilerp_scalar<256, 14>(f3, h * 0.0625f, w * 0.0625f,  orow + 195, lane);
        bilerp_scalar<512, 7>(f4, h * 0.03125f, w * 0.03125f, orow + 451, lane);
    }
}

extern "C" void kernel_launch(void* const* d_in, const int* in_sizes, int n_in,
                              void* d_out, int out_size) {
    const float* coord = (const float*)d_in[0];
    const float* f1 = (const float*)d_in[1];
    const float* f2 = (const float*)d_in[2];
    const float* f3 = (const float*)d_in[3];
    const float* f4 = (const float*)d_in[4];
    float* out = (float*)d_out;

    int N = in_sizes[0] / 3;

    int blocks = (N + 7) / 8;  // 8 warps/block, 1 point/warp
    graph_projection_kernel<<<blocks, 256>>>(coord, f1, f2, f3, f4, out, N);
}